// round 1
// baseline (speedup 1.0000x reference)
#include <cuda_runtime.h>

// Problem constants (fixed shapes for this problem)
#define BB 32          // batch
#define FF 35          // features
#define SS 80          // max target length
#define NC (2*FF+1)    // 71 logit channels
#define NPAIR (BB*FF)  // 1120 independent CTC chains
#define NEGF 0.0f      // impossible path == 0 in linear domain

__device__ float g_loss[NPAIR];

__device__ __forceinline__ float frcp(float x) {
    float r; asm("rcp.approx.f32 %0, %1;" : "=f"(r) : "f"(x)); return r;
}

__global__ __launch_bounds__(128, 8)
void ctc_fwd_kernel(const float* __restrict__ logits,
                    const int*   __restrict__ targets,
                    const int*   __restrict__ in_len,
                    const int*   __restrict__ tgt_len,
                    int T)
{
    const unsigned FM = 0xffffffffu;
    int warp = (blockIdx.x * blockDim.x + threadIdx.x) >> 5;
    int lane = threadIdx.x & 31;
    if (warp >= NPAIR) return;

    int b = warp / FF;
    int f = warp - b * FF;
    int tl  = tgt_len[warp];
    int Lv  = 2 * tl + 1;               // number of valid extended states
    int Tin = in_len[b];
    if (Tin > T) Tin = T;

    // ------- per-state constants (6 states per lane: l = lane*6 + j) -------
    int l0 = lane * 6;
    const int* tg = targets + (size_t)warp * SS;

    float m0 = (l0 + 0 < Lv) ? 1.f : 0.f;
    float m1 = (l0 + 1 < Lv) ? 1.f : 0.f;
    float m2 = (l0 + 2 < Lv) ? 1.f : 0.f;
    float m3 = (l0 + 3 < Lv) ? 1.f : 0.f;
    float m4 = (l0 + 4 < Lv) ? 1.f : 0.f;
    float m5 = (l0 + 5 < Lv) ? 1.f : 0.f;

    // odd states: label = targets[(l-1)/2] in {0,1}; skip if l>=3 && label != prev label
    float w1 = 0.f, w3 = 0.f, w5 = 0.f;
    float sk1 = 0.f, sk3 = 0.f, sk5 = 0.f;
    {
        int l = l0 + 1;
        if (l < Lv) { int s = (l - 1) >> 1; int tv = tg[s];
            w1 = (float)tv; sk1 = (l >= 3 && tg[s - 1] != tv) ? 1.f : 0.f; }
        l = l0 + 3;
        if (l < Lv) { int s = (l - 1) >> 1; int tv = tg[s];
            w3 = (float)tv; sk3 = (l >= 3 && tg[s - 1] != tv) ? 1.f : 0.f; }
        l = l0 + 5;
        if (l < Lv) { int s = (l - 1) >> 1; int tv = tg[s];
            w5 = (float)tv; sk5 = (l >= 3 && tg[s - 1] != tv) ? 1.f : 0.f; }
    }

    // ------- init with t = 0 emissions -------
    float A0 = 0.f, A1 = 0.f, A2 = 0.f, A3 = 0.f, A4 = 0.f, A5 = 0.f;
    {
        const float* lg = logits + (size_t)b * NC;   // t = 0
        float pos = lg[f], neg = lg[FF + f], blk = lg[2 * FF];
        float mm = fmaxf(pos, fmaxf(neg, blk));
        float e0 = __expf(pos - mm), e1 = __expf(neg - mm), e2 = __expf(blk - mm);
        float r  = frcp(e0 + e1 + e2);
        float p0 = e0 * r, p1 = e1 * r, p2 = e2 * r;
        float pd = p1 - p0;
        if (lane == 0) {
            A0 = p2 * m0;                       // state 0: blank
            A1 = fmaf(w1, pd, p0) * m1;         // state 1: first label (0 if tl==0)
        }
    }

    // ------- time recursion -------
    int E = 0;   // accumulated power-of-2 exponent (exact)
    for (int tb = 1; tb < Tin; tb += 32) {
        int tt = tb + lane;
        float LP = 0.f, LN = 0.f, LB = 0.f;
        if (tt < Tin) {
            const float* lg = logits + ((size_t)tt * BB + b) * NC;
            LP = lg[f]; LN = lg[FF + f]; LB = lg[2 * FF];
        }
        int ns = Tin - tb; if (ns > 32) ns = 32;

        #pragma unroll 4
        for (int i = 0; i < ns; i++) {
            float pos = __shfl_sync(FM, LP, i);
            float neg = __shfl_sync(FM, LN, i);
            float blk = __shfl_sync(FM, LB, i);
            float mm = fmaxf(pos, fmaxf(neg, blk));
            float e0 = __expf(pos - mm), e1 = __expf(neg - mm), e2 = __expf(blk - mm);
            float r  = frcp(e0 + e1 + e2);
            float p0 = e0 * r, p1 = e1 * r, p2 = e2 * r;
            float pd = p1 - p0;

            float a5p = __shfl_up_sync(FM, A5, 1);   // prev lane's state l0-1
            if (lane == 0) a5p = 0.f;

            float eo1 = fmaf(w1, pd, p0);
            float eo3 = fmaf(w3, pd, p0);
            float eo5 = fmaf(w5, pd, p0);

            float n0 = (A0 + a5p) * p2 * m0;
            float n1 = fmaf(sk1, a5p, A1 + A0) * eo1 * m1;
            float n2 = (A2 + A1) * p2 * m2;
            float n3 = fmaf(sk3, A1, A3 + A2) * eo3 * m3;
            float n4 = (A4 + A3) * p2 * m4;
            float n5 = fmaf(sk5, A3, A5 + A4) * eo5 * m5;
            A0 = n0; A1 = n1; A2 = n2; A3 = n3; A4 = n4; A5 = n5;

            if ((i & 3) == 3) {      // exact power-of-2 rescale every 4 steps
                float mx = fmaxf(fmaxf(fmaxf(A0, A1), fmaxf(A2, A3)), fmaxf(A4, A5));
                mx = fmaxf(mx, __shfl_xor_sync(FM, mx, 16));
                mx = fmaxf(mx, __shfl_xor_sync(FM, mx, 8));
                mx = fmaxf(mx, __shfl_xor_sync(FM, mx, 4));
                mx = fmaxf(mx, __shfl_xor_sync(FM, mx, 2));
                mx = fmaxf(mx, __shfl_xor_sync(FM, mx, 1));
                int ex = __float_as_int(mx) >> 23;
                if (ex > 0 && ex != 127) {
                    float sc = __int_as_float((254 - ex) << 23);   // exact 2^(127-ex)
                    E += ex - 127;
                    A0 *= sc; A1 *= sc; A2 *= sc; A3 *= sc; A4 *= sc; A5 *= sc;
                }
            }
        }
    }

    // ------- final gather: alpha[2*tl] + alpha[2*tl - 1] -------
    int il = 2 * tl;
    float last = 0.f, prv = 0.f;
    { int l = l0 + 0; if (l == il) last = A0; if (l == il - 1) prv = A0; }
    { int l = l0 + 1; if (l == il) last = A1; if (l == il - 1) prv = A1; }
    { int l = l0 + 2; if (l == il) last = A2; if (l == il - 1) prv = A2; }
    { int l = l0 + 3; if (l == il) last = A3; if (l == il - 1) prv = A3; }
    { int l = l0 + 4; if (l == il) last = A4; if (l == il - 1) prv = A4; }
    { int l = l0 + 5; if (l == il) last = A5; if (l == il - 1) prv = A5; }
    for (int o = 16; o; o >>= 1) {
        last += __shfl_xor_sync(FM, last, o);
        prv  += __shfl_xor_sync(FM, prv,  o);
    }
    if (lane == 0) {
        float s = last + prv;     // prv stays 0 when tl == 0 (index -1 never matched)
        float lossv = 0.f;
        if (s > 0.f)
            lossv = -(__logf(s) + (float)E * 0.6931471805599453f);
        float tlf = fmaxf((float)tl, 1.f);
        g_loss[warp] = lossv / tlf;
    }
}

__global__ void reduce_kernel(float* __restrict__ out)
{
    __shared__ float sm[256];
    float v = 0.f;
    for (int i = threadIdx.x; i < NPAIR; i += 256) v += g_loss[i];
    sm[threadIdx.x] = v;
    __syncthreads();
    for (int o = 128; o; o >>= 1) {
        if (threadIdx.x < o) sm[threadIdx.x] += sm[threadIdx.x + o];
        __syncthreads();
    }
    if (threadIdx.x == 0) out[0] = sm[0] * (1.0f / (float)BB);
}

extern "C" void kernel_launch(void* const* d_in, const int* in_sizes, int n_in,
                              void* d_out, int out_size)
{
    const float* logits  = (const float*)d_in[0];
    const int*   targets = (const int*)d_in[1];
    const int*   in_len  = (const int*)d_in[2];
    const int*   tgt_len = (const int*)d_in[3];
    float* out = (float*)d_out;

    int T = in_sizes[0] / (BB * NC);   // 600

    // 1120 warps -> 280 blocks of 128 threads (4 warps/block)
    ctc_fwd_kernel<<<(NPAIR + 3) / 4, 128>>>(logits, targets, in_len, tgt_len, T);
    reduce_kernel<<<1, 256>>>(out);
}

// round 2
// speedup vs baseline: 1.6931x; 1.6931x over previous
#include <cuda_runtime.h>

#define BB 32
#define FF 35
#define SS 80
#define NC (2*FF+1)          // 71
#define NPAIR (BB*FF)        // 1120 chains
#define NW (NPAIR/2)         // 560 warps (2 chains per warp, packed f32x2)
#define LN2F 0.6931471805599453f

typedef unsigned long long u64;

__device__ float g_loss[NPAIR];
__device__ unsigned g_count = 0;

// ---- packed f32x2 helpers (Blackwell FFMA2 path) ----
__device__ __forceinline__ u64 pk2(float x, float y) {
    u64 r; asm("mov.b64 %0, {%1,%2};" : "=l"(r) : "f"(x), "f"(y)); return r;
}
__device__ __forceinline__ void up2(u64 v, float& x, float& y) {
    asm("mov.b64 {%0,%1}, %2;" : "=f"(x), "=f"(y) : "l"(v));
}
__device__ __forceinline__ u64 add2(u64 a, u64 b) {
    u64 r; asm("add.rn.f32x2 %0, %1, %2;" : "=l"(r) : "l"(a), "l"(b)); return r;
}
__device__ __forceinline__ u64 mul2(u64 a, u64 b) {
    u64 r; asm("mul.rn.f32x2 %0, %1, %2;" : "=l"(r) : "l"(a), "l"(b)); return r;
}
__device__ __forceinline__ u64 fma2_(u64 a, u64 b, u64 c) {
    u64 r; asm("fma.rn.f32x2 %0, %1, %2, %3;" : "=l"(r) : "l"(a), "l"(b), "l"(c)); return r;
}

__global__ __launch_bounds__(128, 1)
void ctc_fwd(const float* __restrict__ logits,
             const int*   __restrict__ targets,
             const int*   __restrict__ in_len,
             const int*   __restrict__ tgt_len,
             int T, float* __restrict__ out)
{
    __shared__ ulonglong2 sE[4][32];   // (e0A,e0B),(pdA,pdB) per step
    __shared__ u64        sE2[4][32];  // (e2A,e2B) per step
    __shared__ float      sred[128];
    __shared__ int        sflag;

    const unsigned FM = 0xffffffffu;
    const int widb = threadIdx.x >> 5;
    const int lane = threadIdx.x & 31;
    const int gw = blockIdx.x * 4 + widb;   // 0..559 (grid is exactly 140 blocks)

    const int cA = gw * 2, cB = cA + 1;
    const int bA = cA / FF, fA = cA - bA * FF;
    const int bB = cB / FF, fB = cB - bB * FF;
    const int tlA = tgt_len[cA], tlB = tgt_len[cB];
    const int LvA = 2 * tlA + 1, LvB = 2 * tlB + 1;
    int TinA = in_len[bA]; if (TinA > T) TinA = T;
    int TinB = in_len[bB]; if (TinB > T) TinB = T;
    const int Tmin = (TinA < TinB) ? TinA : TinB;
    const int Tmax = (TinA > TinB) ? TinA : TinB;

    const int l0 = lane * 6;
    const int* tgA = targets + (size_t)cA * SS;
    const int* tgB = targets + (size_t)cB * SS;

    // per-lane packed constants: masks (6 states), label weight + skip (odd states)
    u64 M[6], W[3], SK[3];
    #pragma unroll
    for (int j = 0; j < 6; j++)
        M[j] = pk2((l0 + j < LvA) ? 1.f : 0.f, (l0 + j < LvB) ? 1.f : 0.f);
    #pragma unroll
    for (int j = 0; j < 3; j++) {
        int l = l0 + 2 * j + 1;
        float wa = 0.f, ska = 0.f, wb = 0.f, skb = 0.f;
        if (l < LvA) { int s = (l - 1) >> 1; int tv = tgA[s];
            wa = (float)tv; ska = (l >= 3 && tgA[s - 1] != tv) ? 1.f : 0.f; }
        if (l < LvB) { int s = (l - 1) >> 1; int tv = tgB[s];
            wb = (float)tv; skb = (l >= 3 && tgB[s - 1] != tv) ? 1.f : 0.f; }
        W[j] = pk2(wa, wb); SK[j] = pk2(ska, skb);
    }

    const float* pA = logits + (size_t)bA * NC + fA;   // chain A pos channel, t=0
    const float* pB = logits + (size_t)bB * NC + fB;
    const int oblA = 2 * FF - fA;   // offset from pos to blank
    const int oblB = 2 * FF - fB;
    const int TS = BB * NC;         // per-timestep stride (floats)

    u64 A0 = 0, A1 = 0, A2 = 0, A3 = 0, A4 = 0, A5 = 0;
    float ZaccA = 1.f, ZaccB = 1.f;
    int ezA = 0, ezB = 0, EA = 0, EB = 0;

    // ---- t = 0 init (unnormalized emissions; Z folded into lane-0 accumulator) ----
    {
        float e0a = __expf(pA[0]), e1a = __expf(pA[FF]), e2a = __expf(pA[oblA]);
        float e0b = __expf(pB[0]), e1b = __expf(pB[FF]), e2b = __expf(pB[oblB]);
        if (lane == 0) {
            A0 = pk2(e2a, e2b);
            A1 = mul2(fma2_(W[0], pk2(e1a - e0a, e1b - e0b), pk2(e0a, e0b)), M[1]);
            ZaccA = e0a + e1a + e2a;
            ZaccB = e0b + e1b + e2b;
        }
    }

    // ---- prefetch for the first block (t = 1 + lane) ----
    float rpA = 0.f, rnA = 0.f, rbA = 0.f, rpB = 0.f, rnB = 0.f, rbB = 0.f;
    {
        int tt = 1 + lane;
        if (tt < Tmax) {
            const float* qa = pA + (size_t)tt * TS;
            rpA = qa[0]; rnA = qa[FF]; rbA = qa[oblA];
            const float* qb = pB + (size_t)tt * TS;
            rpB = qb[0]; rnB = qb[FF]; rbB = qb[oblB];
        }
    }

    auto STEP = [&](int i) {
        ulonglong2 ep = sE[widb][i];       // .x=(e0A,e0B), .y=(pdA,pdB)
        u64 e2 = sE2[widb][i];
        u64 a5p = __shfl_up_sync(FM, A5, 1);
        if (lane == 0) a5p = 0ull;
        u64 eo1 = fma2_(W[0], ep.y, ep.x);
        u64 eo3 = fma2_(W[1], ep.y, ep.x);
        u64 eo5 = fma2_(W[2], ep.y, ep.x);
        u64 n0 = mul2(add2(A0, a5p), e2);
        u64 n1 = mul2(fma2_(SK[0], a5p, add2(A1, A0)), eo1);
        u64 n2 = mul2(add2(A2, A1), e2);
        u64 n3 = mul2(fma2_(SK[1], A1, add2(A3, A2)), eo3);
        u64 n4 = mul2(add2(A4, A3), e2);
        u64 n5 = mul2(fma2_(SK[2], A3, add2(A5, A4)), eo5);
        A0 = n0; A1 = n1; A2 = n2; A3 = n3; A4 = n4; A5 = n5;
    };

    auto RESCALE = [&]() {
        // zero invalid states, then exact power-of-2 rescale per chain (pivot = warp sum)
        A0 = mul2(A0, M[0]); A1 = mul2(A1, M[1]); A2 = mul2(A2, M[2]);
        A3 = mul2(A3, M[3]); A4 = mul2(A4, M[4]); A5 = mul2(A5, M[5]);
        u64 s = add2(add2(add2(A0, A1), add2(A2, A3)), add2(A4, A5));
        #pragma unroll
        for (int o = 16; o; o >>= 1) s = add2(s, __shfl_xor_sync(FM, s, o));
        float sa, sb; up2(s, sa, sb);
        int exa = (__float_as_int(sa) >> 23) & 0xff;
        int exb = (__float_as_int(sb) >> 23) & 0xff;
        exa = min(max(exa, 1), 253); exb = min(max(exb, 1), 253);
        EA += exa - 127; EB += exb - 127;
        u64 sc = pk2(__int_as_float((254 - exa) << 23), __int_as_float((254 - exb) << 23));
        A0 = mul2(A0, sc); A1 = mul2(A1, sc); A2 = mul2(A2, sc);
        A3 = mul2(A3, sc); A4 = mul2(A4, sc); A5 = mul2(A5, sc);
    };

    // ---- time recursion in 32-step blocks ----
    for (int tb = 1; tb < Tmax; tb += 32) {
        int ns = Tmax - tb; if (ns > 32) ns = 32;

        float e0a = __expf(rpA), e1a = __expf(rnA), e2a = __expf(rbA);
        float e0b = __expf(rpB), e1b = __expf(rnB), e2b = __expf(rbB);
        __syncwarp();
        sE[widb][lane]  = make_ulonglong2(pk2(e0a, e0b), pk2(e1a - e0a, e1b - e0b));
        sE2[widb][lane] = pk2(e2a, e2b);

        // per-lane Z accumulation (exact exponent tracking; one active t per lane)
        int tt = tb + lane;
        if (tt < TinA) {
            ZaccA *= (e0a + e1a + e2a);
            int bt = __float_as_int(ZaccA);
            ezA += (bt >> 23) - 127;
            ZaccA = __int_as_float((bt & 0x7fffff) | 0x3f800000);
        }
        if (tt < TinB) {
            ZaccB *= (e0b + e1b + e2b);
            int bt = __float_as_int(ZaccB);
            ezB += (bt >> 23) - 127;
            ZaccB = __int_as_float((bt & 0x7fffff) | 0x3f800000);
        }

        // prefetch next block
        int tn = tb + 32 + lane;
        if (tn < Tmax) {
            const float* qa = pA + (size_t)tn * TS;
            rpA = qa[0]; rnA = qa[FF]; rbA = qa[oblA];
            const float* qb = pB + (size_t)tn * TS;
            rpB = qb[0]; rnB = qb[FF]; rbB = qb[oblB];
        }
        __syncwarp();

        if (tb + 32 <= Tmin) {
            #pragma unroll 8
            for (int i = 0; i < 32; i++) {
                STEP(i);
                if ((i & 7) == 7) RESCALE();
            }
        } else {
            // tail / unequal-length path: per-chain freeze beyond Tin
            for (int i = 0; i < ns; i++) {
                int t = tb + i;
                u64 o0 = A0, o1 = A1, o2 = A2, o3 = A3, o4 = A4, o5 = A5;
                STEP(i);
                bool ga = (t < TinA), gb = (t < TinB);
                if (!(ga && gb)) {
                    float nx, ny, ox, oy;
                    #define SELST(N, O) { up2(N, nx, ny); up2(O, ox, oy); \
                        N = pk2(ga ? nx : ox, gb ? ny : oy); }
                    SELST(A0, o0) SELST(A1, o1) SELST(A2, o2)
                    SELST(A3, o3) SELST(A4, o4) SELST(A5, o5)
                    #undef SELST
                }
                if ((i & 7) == 7) RESCALE();
            }
        }
    }

    // ---- final gather: alpha[2*tl] + alpha[2*tl-1] per chain ----
    float lastA = 0.f, prvA = 0.f, lastB = 0.f, prvB = 0.f;
    {
        int ilA = 2 * tlA, ilB = 2 * tlB;
        float x, y;
        #define GATH(j, R) { up2(R, x, y); int l = l0 + j; \
            if (l == ilA) lastA = x; if (l == ilA - 1) prvA = x; \
            if (l == ilB) lastB = y; if (l == ilB - 1) prvB = y; }
        GATH(0, A0) GATH(1, A1) GATH(2, A2) GATH(3, A3) GATH(4, A4) GATH(5, A5)
        #undef GATH
    }
    u64 fs = pk2(lastA + prvA, lastB + prvB);
    u64 lz = pk2(__logf(ZaccA) + (float)ezA * LN2F,
                 __logf(ZaccB) + (float)ezB * LN2F);
    #pragma unroll
    for (int o = 16; o; o >>= 1) {
        fs = add2(fs, __shfl_xor_sync(FM, fs, o));
        lz = add2(lz, __shfl_xor_sync(FM, lz, o));
    }
    if (lane == 0) {
        float sa, sb, za, zb;
        up2(fs, sa, sb); up2(lz, za, zb);
        float lossA = 0.f, lossB = 0.f;
        if (sa > 0.f) lossA = za - (__logf(sa) + (float)EA * LN2F);
        if (sb > 0.f) lossB = zb - (__logf(sb) + (float)EB * LN2F);
        g_loss[cA] = lossA / fmaxf((float)tlA, 1.f);
        g_loss[cB] = lossB / fmaxf((float)tlB, 1.f);
    }

    // ---- fused grid reduction: last-arriving block sums g_loss ----
    __syncthreads();
    if (threadIdx.x == 0) {
        __threadfence();
        unsigned v = atomicAdd(&g_count, 1u);
        sflag = (v == gridDim.x - 1u) ? 1 : 0;
    }
    __syncthreads();
    if (sflag) {
        __threadfence();
        float acc = 0.f;
        for (int i = threadIdx.x; i < NPAIR; i += 128) acc += g_loss[i];
        sred[threadIdx.x] = acc;
        __syncthreads();
        #pragma unroll
        for (int o = 64; o; o >>= 1) {
            if (threadIdx.x < o) sred[threadIdx.x] += sred[threadIdx.x + o];
            __syncthreads();
        }
        if (threadIdx.x == 0) {
            out[0] = sred[0] * (1.0f / (float)BB);
            g_count = 0;   // reset for next graph replay
            __threadfence();
        }
    }
}

extern "C" void kernel_launch(void* const* d_in, const int* in_sizes, int n_in,
                              void* d_out, int out_size)
{
    const float* logits  = (const float*)d_in[0];
    const int*   targets = (const int*)d_in[1];
    const int*   in_len  = (const int*)d_in[2];
    const int*   tgt_len = (const int*)d_in[3];
    float* out = (float*)d_out;

    int T = in_sizes[0] / (BB * NC);   // 600

    // 560 warps = 140 blocks x 4 warps: exactly one warp per SMSP on 140 SMs
    ctc_fwd<<<NW / 4, 128>>>(logits, targets, in_len, tgt_len, T, out);
}

// round 4
// speedup vs baseline: 2.2693x; 1.3403x over previous
#include <cuda_runtime.h>

#define BB 32
#define FF 35
#define SS 80
#define NC (2*FF+1)          // 71
#define NPAIR (BB*FF)        // 1120 chains
#define NW (NPAIR/2)         // 560 warps (2 chains per warp, packed f32x2)
#define LN2F 0.69314718055994530942f

typedef unsigned long long u64;

__device__ float g_loss[NPAIR];
__device__ unsigned g_count = 0;

__device__ __forceinline__ u64 pk2(float x, float y) {
    u64 r; asm("mov.b64 %0, {%1,%2};" : "=l"(r) : "f"(x), "f"(y)); return r;
}
__device__ __forceinline__ void up2(u64 v, float& x, float& y) {
    asm("mov.b64 {%0,%1}, %2;" : "=f"(x), "=f"(y) : "l"(v));
}
__device__ __forceinline__ u64 add2(u64 a, u64 b) {
    u64 r; asm("add.rn.f32x2 %0, %1, %2;" : "=l"(r) : "l"(a), "l"(b)); return r;
}
__device__ __forceinline__ u64 mul2(u64 a, u64 b) {
    u64 r; asm("mul.rn.f32x2 %0, %1, %2;" : "=l"(r) : "l"(a), "l"(b)); return r;
}
__device__ __forceinline__ u64 fma2_(u64 a, u64 b, u64 c) {
    u64 r; asm("fma.rn.f32x2 %0, %1, %2, %3;" : "=l"(r) : "l"(a), "l"(b), "l"(c)); return r;
}
__device__ __forceinline__ float frcp(float x) {
    float r; asm("rcp.approx.f32 %0, %1;" : "=f"(r) : "f"(x)); return r;
}

// mantissa-normalize Z into [1,2), accumulate exponent
#define EXTR(Z, ez) { int _bt = __float_as_int(Z); ez += (_bt >> 23) - 127; \
                      Z = __int_as_float((_bt & 0x7fffff) | 0x3f800000); }

__global__ __launch_bounds__(128, 1)
void ctc_fwd(const float* __restrict__ logits,
             const int*   __restrict__ targets,
             const int*   __restrict__ in_len,
             const int*   __restrict__ tgt_len,
             int T, float* __restrict__ out)
{
    __shared__ ulonglong2 sEE[4][32];   // per step: (e0'A,e0'B), (pd'A,pd'B)
    __shared__ float      sred[128];
    __shared__ int        sflag;

    const unsigned FM = 0xffffffffu;
    const int widb = threadIdx.x >> 5;
    const int lane = threadIdx.x & 31;
    const int gw = blockIdx.x * 4 + widb;      // 0..559

    const int cA = gw * 2, cB = cA + 1;
    const int bA = cA / FF, fA = cA - bA * FF;
    const int bB = cB / FF, fB = cB - bB * FF;
    const int tlA = tgt_len[cA], tlB = tgt_len[cB];
    const int LvA = 2 * tlA + 1, LvB = 2 * tlB + 1;
    int TinA = in_len[bA]; if (TinA > T) TinA = T;
    int TinB = in_len[bB]; if (TinB > T) TinB = T;
    const int Tmin = (TinA < TinB) ? TinA : TinB;
    const int Tmax = (TinA > TinB) ? TinA : TinB;

    const int l0 = lane * 6;
    const int* tgA = targets + (size_t)cA * SS;
    const int* tgB = targets + (size_t)cB * SS;

    u64 M[6], W[3], SK[3];
    #pragma unroll
    for (int j = 0; j < 6; j++)
        M[j] = pk2((l0 + j < LvA) ? 1.f : 0.f, (l0 + j < LvB) ? 1.f : 0.f);
    #pragma unroll
    for (int j = 0; j < 3; j++) {
        int l = l0 + 2 * j + 1;
        float wa = 0.f, ska = 0.f, wb = 0.f, skb = 0.f;
        if (l < LvA) { int s = (l - 1) >> 1; int tv = tgA[s];
            wa = (float)tv; ska = (l >= 3 && tgA[s - 1] != tv) ? 1.f : 0.f; }
        if (l < LvB) { int s = (l - 1) >> 1; int tv = tgB[s];
            wb = (float)tv; skb = (l >= 3 && tgB[s - 1] != tv) ? 1.f : 0.f; }
        W[j] = pk2(wa, wb); SK[j] = pk2(ska, skb);
    }

    const float* pA = logits + (size_t)bA * NC + fA;
    const float* pB = logits + (size_t)bB * NC + fB;
    const int oblA = 2 * FF - fA;
    const int oblB = 2 * FF - fB;
    const int TS = BB * NC;

    u64 A0 = 0, A1 = 0, A2 = 0, A3 = 0, A4 = 0, A5 = 0, a5p = 0;
    float ZaccA = 1.f, ZaccB = 1.f, PaccA = 1.f, PaccB = 1.f;
    int ezA = 0, ezB = 0, epA = 0, epB = 0, EA = 0, EB = 0;

    // ---- t = 0 init (full emissions; Z(0) into lane-0 accumulator) ----
    {
        float e0a = __expf(pA[0]), e1a = __expf(pA[FF]), e2a = __expf(pA[oblA]);
        float e0b = __expf(pB[0]), e1b = __expf(pB[FF]), e2b = __expf(pB[oblB]);
        if (lane == 0) {
            A0 = pk2(e2a, e2b);
            A1 = mul2(fma2_(W[0], pk2(e1a - e0a, e1b - e0b), pk2(e0a, e0b)), M[1]);
            ZaccA = e0a + e1a + e2a;
            ZaccB = e0b + e1b + e2b;
        }
    }

    // ---- prefetch first block (t = 1 + lane) ----
    float rpA = 0.f, rnA = 0.f, rbA = 0.f, rpB = 0.f, rnB = 0.f, rbB = 0.f;
    {
        int tt = 1 + lane;
        if (tt < Tmax) {
            const float* qa = pA + (size_t)tt * TS;
            rpA = qa[0]; rnA = qa[FF]; rbA = qa[oblA];
            const float* qb = pB + (size_t)tt * TS;
            rpB = qb[0]; rnB = qb[FF]; rbB = qb[oblB];
        }
    }

// one CTC step on blank-factored emissions (even states: pure add)
#define STEP(i) { \
    ulonglong2 ep = sEE[widb][i]; \
    u64 t1 = fma2_(W[0], ep.y, ep.x); \
    u64 t3 = fma2_(W[1], ep.y, ep.x); \
    u64 t5 = fma2_(W[2], ep.y, ep.x); \
    u64 n0 = add2(A0, a5p); \
    u64 n1 = mul2(fma2_(SK[0], a5p, add2(A1, A0)), t1); \
    u64 n2 = add2(A2, A1); \
    u64 n3 = mul2(fma2_(SK[1], A1, add2(A3, A2)), t3); \
    u64 n4 = add2(A4, A3); \
    u64 n5 = mul2(fma2_(SK[2], A3, add2(A5, A4)), t5); \
    A0 = n0; A1 = n1; A2 = n2; A3 = n3; A4 = n4; A5 = n5; \
    a5p = __shfl_up_sync(FM, A5, 1); \
    a5p = lane ? a5p : 0ull; }

// apply exact power-of-2 rescale from reduced sum sv; masks folded in; a5p refreshed
#define APPLY(sv) { \
    float sa, sb; up2(sv, sa, sb); \
    int exa = (__float_as_int(sa) >> 23) & 0xff; \
    int exb = (__float_as_int(sb) >> 23) & 0xff; \
    exa = min(max(exa, 1), 253); exb = min(max(exb, 1), 253); \
    EA += exa - 127; EB += exb - 127; \
    u64 sc = pk2(__int_as_float((254 - exa) << 23), __int_as_float((254 - exb) << 23)); \
    A0 = mul2(A0, mul2(sc, M[0])); A1 = mul2(A1, mul2(sc, M[1])); \
    A2 = mul2(A2, mul2(sc, M[2])); A3 = mul2(A3, mul2(sc, M[3])); \
    A4 = mul2(A4, mul2(sc, M[4])); A5 = mul2(A5, mul2(sc, M[5])); \
    a5p = __shfl_up_sync(FM, A5, 1); \
    a5p = lane ? a5p : 0ull; }

    for (int tb = 1; tb < Tmax; tb += 32) {
        int ns = Tmax - tb; if (ns > 32) ns = 32;

        // ---- stage blank-factored emissions; accumulate Z and blank product P ----
        float e0a = __expf(rpA), e1a = __expf(rnA), e2a = __expf(rbA);
        float e0b = __expf(rpB), e1b = __expf(rnB), e2b = __expf(rbB);
        float r2a = frcp(e2a), r2b = frcp(e2b);
        __syncwarp();
        sEE[widb][lane] = make_ulonglong2(pk2(e0a * r2a, e0b * r2b),
                                          pk2((e1a - e0a) * r2a, (e1b - e0b) * r2b));
        int tt = tb + lane;
        if (tt < TinA) { ZaccA *= (e0a + e1a + e2a); EXTR(ZaccA, ezA);
                         PaccA *= e2a;               EXTR(PaccA, epA); }
        if (tt < TinB) { ZaccB *= (e0b + e1b + e2b); EXTR(ZaccB, ezB);
                         PaccB *= e2b;               EXTR(PaccB, epB); }

        // prefetch next block
        int tn = tb + 32 + lane;
        if (tn < Tmax) {
            const float* qa = pA + (size_t)tn * TS;
            rpA = qa[0]; rnA = qa[FF]; rbA = qa[oblA];
            const float* qb = pB + (size_t)tn * TS;
            rpB = qb[0]; rnB = qb[FF]; rbB = qb[oblB];
        }
        __syncwarp();

        if (tb + 32 <= Tmin) {
            // fast path: both chains active for all 32 steps;
            // rescale every 16 steps, butterfly spread over steps 11..15 / 27..31
            u64 sv = 0;
            #pragma unroll
            for (int i = 0; i < 32; i++) {
                STEP(i);
                if (i == 10 || i == 26)
                    sv = add2(add2(add2(A0, A1), add2(A2, A3)), add2(A4, A5));
                if (i == 11 || i == 27) sv = add2(sv, __shfl_xor_sync(FM, sv, 1));
                if (i == 12 || i == 28) sv = add2(sv, __shfl_xor_sync(FM, sv, 2));
                if (i == 13 || i == 29) sv = add2(sv, __shfl_xor_sync(FM, sv, 4));
                if (i == 14 || i == 30) sv = add2(sv, __shfl_xor_sync(FM, sv, 8));
                if (i == 15 || i == 31) {
                    sv = add2(sv, __shfl_xor_sync(FM, sv, 16));
                    APPLY(sv);
                }
            }
        } else {
            // tail / unequal-length path
            for (int i = 0; i < ns; i++) {
                int t = tb + i;
                u64 o0 = A0, o1 = A1, o2 = A2, o3 = A3, o4 = A4, o5 = A5;
                STEP(i);
                bool ga = (t < TinA), gb = (t < TinB);
                if (!(ga && gb)) {
                    float nx, ny, ox, oy;
                    #define SELST(N, O) { up2(N, nx, ny); up2(O, ox, oy); \
                        N = pk2(ga ? nx : ox, gb ? ny : oy); }
                    SELST(A0, o0) SELST(A1, o1) SELST(A2, o2)
                    SELST(A3, o3) SELST(A4, o4) SELST(A5, o5)
                    #undef SELST
                    a5p = __shfl_up_sync(FM, A5, 1);
                    a5p = lane ? a5p : 0ull;
                }
                if ((i & 7) == 7) {
                    u64 sv = add2(add2(add2(A0, A1), add2(A2, A3)), add2(A4, A5));
                    #pragma unroll
                    for (int o = 16; o; o >>= 1)
                        sv = add2(sv, __shfl_xor_sync(FM, sv, o));
                    APPLY(sv);
                }
            }
        }
    }

    // ---- final gather: alpha[2*tl] + alpha[2*tl-1] per chain ----
    float lastA = 0.f, prvA = 0.f, lastB = 0.f, prvB = 0.f;
    {
        int ilA = 2 * tlA, ilB = 2 * tlB;
        float x, y;
        #define GATH(j, R) { up2(R, x, y); int l = l0 + j; \
            if (l == ilA) lastA = x; if (l == ilA - 1) prvA = x; \
            if (l == ilB) lastB = y; if (l == ilB - 1) prvB = y; }
        GATH(0, A0) GATH(1, A1) GATH(2, A2) GATH(3, A3) GATH(4, A4) GATH(5, A5)
        #undef GATH
    }
    u64 fs = pk2(lastA + prvA, lastB + prvB);
    // per-lane: log Z - log P  (blank product re-multiplied back in)
    u64 lz = pk2(__logf(ZaccA) - __logf(PaccA) + (float)(ezA - epA) * LN2F,
                 __logf(ZaccB) - __logf(PaccB) + (float)(ezB - epB) * LN2F);
    #pragma unroll
    for (int o = 16; o; o >>= 1) {
        fs = add2(fs, __shfl_xor_sync(FM, fs, o));
        lz = add2(lz, __shfl_xor_sync(FM, lz, o));
    }
    if (lane == 0) {
        float sa, sb, za, zb;
        up2(fs, sa, sb); up2(lz, za, zb);
        float lossA = 0.f, lossB = 0.f;
        if (sa > 0.f) lossA = za - (__logf(sa) + (float)EA * LN2F);
        if (sb > 0.f) lossB = zb - (__logf(sb) + (float)EB * LN2F);
        g_loss[cA] = lossA / fmaxf((float)tlA, 1.f);
        g_loss[cB] = lossB / fmaxf((float)tlB, 1.f);
    }

    // ---- fused grid reduction ----
    __syncthreads();
    if (threadIdx.x == 0) {
        __threadfence();
        unsigned v = atomicAdd(&g_count, 1u);
        sflag = (v == gridDim.x - 1u) ? 1 : 0;
    }
    __syncthreads();
    if (sflag) {
        __threadfence();
        float acc = 0.f;
        for (int i = threadIdx.x; i < NPAIR; i += 128) acc += g_loss[i];
        sred[threadIdx.x] = acc;
        __syncthreads();
        #pragma unroll
        for (int o = 64; o; o >>= 1) {
            if (threadIdx.x < o) sred[threadIdx.x] += sred[threadIdx.x + o];
            __syncthreads();
        }
        if (threadIdx.x == 0) {
            out[0] = sred[0] * (1.0f / (float)BB);
            g_count = 0;
            __threadfence();
        }
    }
}

extern "C" void kernel_launch(void* const* d_in, const int* in_sizes, int n_in,
                              void* d_out, int out_size)
{
    const float* logits  = (const float*)d_in[0];
    const int*   targets = (const int*)d_in[1];
    const int*   in_len  = (const int*)d_in[2];
    const int*   tgt_len = (const int*)d_in[3];
    float* out = (float*)d_out;

    int T = in_sizes[0] / (BB * NC);   // 600

    ctc_fwd<<<NW / 4, 128>>>(logits, targets, in_len, tgt_len, T, out);
}